// round 1
// baseline (speedup 1.0000x reference)
#include <cuda_runtime.h>

// MultiHeadAttention collapse:
//   reference einsum 'bhtl,bthd->bhtd' sums A over l while v has no l index,
//   so o = rowsum(softmax) * v = v (permuted). Full computation reduces to:
//   y = gather_perm(x @ Wv) @ Wo^T
//
// B=2, T=2048, D=1024, H=16, DK=64.  Two GEMMs of 4096x1024x1024 fp32.

#define TB 2
#define TT 2048
#define TD 1024
#define MTOT (TB * TT)   // 4096

// scratch for V = x @ Wv   (16 MB, static device array per harness rules)
__device__ float g_V[MTOT * TD];

// ---------------------------------------------------------------------------
// GEMM1 (NN): g_V = x[4096,1024] @ Wv[1024,1024]
// 128x128 tile, K-tile 8, 256 threads, 8x8 per thread
// ---------------------------------------------------------------------------
__global__ __launch_bounds__(256, 2)
void gemm_xWv(const float* __restrict__ A, const float* __restrict__ Bw) {
    __shared__ float As[8][132];
    __shared__ float Bs[8][132];
    const int N = TD, K = TD;

    const int bm = blockIdx.y * 128;
    const int bn = blockIdx.x * 128;
    const int tid = threadIdx.x;
    const int tx = tid & 15, ty = tid >> 4;

    // A tile load: 128 rows x 8 k  -> one float4 per thread along K
    const int arow = tid >> 1;
    const int ak   = (tid & 1) * 4;
    // B tile load: 8 k-rows x 128 n -> one float4 per thread along N
    const int bk   = tid >> 5;
    const int bn4  = (tid & 31) * 4;

    const float* Aptr = A + (size_t)(bm + arow) * K + ak;
    const float* Bptr = Bw + (size_t)bk * N + bn + bn4;

    float acc[8][8];
#pragma unroll
    for (int i = 0; i < 8; i++)
#pragma unroll
        for (int j = 0; j < 8; j++) acc[i][j] = 0.f;

    for (int k0 = 0; k0 < K; k0 += 8) {
        float4 av = *(const float4*)(Aptr + k0);
        float4 bv = *(const float4*)(Bptr + (size_t)k0 * N);
        As[ak + 0][arow] = av.x;
        As[ak + 1][arow] = av.y;
        As[ak + 2][arow] = av.z;
        As[ak + 3][arow] = av.w;
        *(float4*)&Bs[bk][bn4] = bv;
        __syncthreads();

#pragma unroll
        for (int k = 0; k < 8; k++) {
            float a[8], b[8];
#pragma unroll
            for (int i = 0; i < 8; i++) a[i] = As[k][ty * 8 + i];
#pragma unroll
            for (int j = 0; j < 8; j++) b[j] = Bs[k][tx * 8 + j];
#pragma unroll
            for (int i = 0; i < 8; i++)
#pragma unroll
                for (int j = 0; j < 8; j++) acc[i][j] += a[i] * b[j];
        }
        __syncthreads();
    }

#pragma unroll
    for (int i = 0; i < 8; i++) {
        float* crow = g_V + (size_t)(bm + ty * 8 + i) * N + bn + tx * 8;
        float4 v0 = make_float4(acc[i][0], acc[i][1], acc[i][2], acc[i][3]);
        float4 v1 = make_float4(acc[i][4], acc[i][5], acc[i][6], acc[i][7]);
        *(float4*)(crow)     = v0;
        *(float4*)(crow + 4) = v1;
    }
}

// ---------------------------------------------------------------------------
// GEMM2 (gather + NT): out[m, j] = sum_k Ag[m,k] * Wo[j,k]
//   Ag[m,k] = V[b, r*16 + (k>>6), h*64 + (k&63)]
//   with b = m>>11, t2 = m&2047, h = t2>>7, r = t2&127
// ---------------------------------------------------------------------------
__global__ __launch_bounds__(256, 2)
void gemm_gather_Wo(const float* __restrict__ Wo, float* __restrict__ C) {
    __shared__ float As[8][132];
    __shared__ float Bs[8][132];
    const int N = TD, K = TD;

    const int bm = blockIdx.y * 128;
    const int bn = blockIdx.x * 128;
    const int tid = threadIdx.x;
    const int tx = tid & 15, ty = tid >> 4;

    // gathered-A tile load mapping (same shape as GEMM1 A load)
    const int arow = tid >> 1;
    const int ak   = (tid & 1) * 4;
    const int m  = bm + arow;
    const int b  = m >> 11;
    const int t2 = m & 2047;
    const int h  = t2 >> 7;
    const int r  = t2 & 127;
    const float* Vbase = g_V + (size_t)((b << 11) + r * 16) * TD + h * 64;

    // Wo tile load: 128 j-rows x 8 k -> one float4 per thread along K, transpose to smem
    const int brow  = tid >> 1;
    const int bkoff = (tid & 1) * 4;
    const float* Wptr = Wo + (size_t)(bn + brow) * K + bkoff;

    float acc[8][8];
#pragma unroll
    for (int i = 0; i < 8; i++)
#pragma unroll
        for (int j = 0; j < 8; j++) acc[i][j] = 0.f;

    for (int k0 = 0; k0 < K; k0 += 8) {
        const int kg = k0 + ak;
        // gather: 16 consecutive V rows per out-row, 64-col band; float4 stays in-row
        float4 av = *(const float4*)(Vbase + ((kg >> 6) << 10) + (kg & 63));
        float4 bv = *(const float4*)(Wptr + k0);
        As[ak + 0][arow] = av.x;
        As[ak + 1][arow] = av.y;
        As[ak + 2][arow] = av.z;
        As[ak + 3][arow] = av.w;
        Bs[bkoff + 0][brow] = bv.x;
        Bs[bkoff + 1][brow] = bv.y;
        Bs[bkoff + 2][brow] = bv.z;
        Bs[bkoff + 3][brow] = bv.w;
        __syncthreads();

#pragma unroll
        for (int k = 0; k < 8; k++) {
            float a[8], bb[8];
#pragma unroll
            for (int i = 0; i < 8; i++) a[i] = As[k][ty * 8 + i];
#pragma unroll
            for (int j = 0; j < 8; j++) bb[j] = Bs[k][tx * 8 + j];
#pragma unroll
            for (int i = 0; i < 8; i++)
#pragma unroll
                for (int j = 0; j < 8; j++) acc[i][j] += a[i] * bb[j];
        }
        __syncthreads();
    }

#pragma unroll
    for (int i = 0; i < 8; i++) {
        float* crow = C + (size_t)(bm + ty * 8 + i) * N + bn + tx * 8;
        float4 v0 = make_float4(acc[i][0], acc[i][1], acc[i][2], acc[i][3]);
        float4 v1 = make_float4(acc[i][4], acc[i][5], acc[i][6], acc[i][7]);
        *(float4*)(crow)     = v0;
        *(float4*)(crow + 4) = v1;
    }
}

// ---------------------------------------------------------------------------
// inputs (metadata order): x, mask, Wq, Wk, Wv, Wo   -> output fp32 [B,T,D]
// Q/K/mask/softmax are algebraically dead (softmax rowsum == 1).
// ---------------------------------------------------------------------------
extern "C" void kernel_launch(void* const* d_in, const int* in_sizes, int n_in,
                              void* d_out, int out_size) {
    const float* x  = (const float*)d_in[0];
    const float* Wv = (const float*)d_in[4];
    const float* Wo = (const float*)d_in[5];
    float* out = (float*)d_out;

    dim3 grid(TD / 128, MTOT / 128);  // (8, 32)
    dim3 block(256);

    gemm_xWv<<<grid, block>>>(x, Wv);
    gemm_gather_Wo<<<grid, block>>>(Wo, out);
}

// round 3
// speedup vs baseline: 2.2491x; 2.2491x over previous
#include <cuda_runtime.h>
#include <cuda_bf16.h>
#include <cstdint>

// y = gather_perm(x @ Wv) @ Wo^T   (softmax rowsum == 1 collapse, validated R1:
//   einsum 'bhtl,bthd->bhtd' contracts A over l with no l on v => rowsum(A)=1)
// tcgen05 is NOT available (harness PTX targets sm_103, no 'a' suffix) =>
// use sm_80-class tensor path: mma.sync.m16n8k16.bf16 + ldmatrix + cp.async.
// Precision: bf16 hi/lo split, C = Ah*Bh + Ah*Bl + Al*Bh  (err ~1e-5 << 1e-3)

#define MTOT 4096
#define DD   1024
#define KS   40                  // padded smem row stride (bf16): 80B, conflict-free ldmatrix
#define STG_MAT  (128 * KS * 2)  // 10240 B per matrix tile
#define OFF_AH   0
#define OFF_AL   (1 * STG_MAT)
#define OFF_BH   (2 * STG_MAT)
#define OFF_BL   (3 * STG_MAT)
#define STG_BYTES (4 * STG_MAT)  // 40960 B / stage
#define SMEM_SZ   (2 * STG_BYTES)
#define NCHUNK   (DD / 32)       // 32 k-chunks of BK=32

__device__ __nv_bfloat16 g_xhi[MTOT * DD], g_xlo[MTOT * DD];
__device__ __nv_bfloat16 g_wvthi[DD * DD], g_wvtlo[DD * DD];
__device__ __nv_bfloat16 g_wohi[DD * DD],  g_wolo[DD * DD];
__device__ __nv_bfloat16 g_vhi[MTOT * DD], g_vlo[MTOT * DD];

// ------------------------------------------------------------------ asm utils
static __device__ __forceinline__ uint32_t smem_u32(const void* p) {
    uint32_t a;
    asm("{ .reg .u64 t; cvta.to.shared.u64 t, %1; cvt.u32.u64 %0, t; }" : "=r"(a) : "l"(p));
    return a;
}
#define CP16(s, g) \
    asm volatile("cp.async.cg.shared.global [%0], [%1], 16;" :: "r"(s), "l"(g))
#define CP_COMMIT() asm volatile("cp.async.commit_group;")
#define CP_WAIT1()  asm volatile("cp.async.wait_group 1;")
#define CP_WAIT0()  asm volatile("cp.async.wait_group 0;")

#define LDSM4(r, addr) \
    asm volatile("ldmatrix.sync.aligned.m8n8.x4.shared.b16 {%0,%1,%2,%3}, [%4];" \
                 : "=r"((r)[0]), "=r"((r)[1]), "=r"((r)[2]), "=r"((r)[3]) : "r"(addr))

#define MMA(d, a, b0, b1) \
    asm volatile("mma.sync.aligned.m16n8k16.row.col.f32.bf16.bf16.f32 " \
                 "{%0,%1,%2,%3}, {%4,%5,%6,%7}, {%8,%9}, {%0,%1,%2,%3};" \
                 : "+f"((d)[0]), "+f"((d)[1]), "+f"((d)[2]), "+f"((d)[3]) \
                 : "r"((a)[0]), "r"((a)[1]), "r"((a)[2]), "r"((a)[3]), "r"(b0), "r"(b1))

// ------------------------------------------------------------------ GEMM
// MODE 0: V = x @ WvT^T  (A = g_xhi/lo [m][k], B = g_wvthi/lo [n][k]) -> g_vhi/lo
// MODE 1: out = gather(V) @ Wo^T (A gathered from g_vhi/lo, B = g_wohi/lo) -> fp32
template<int MODE>
__global__ void __launch_bounds__(128)
gemm_hmma(float* __restrict__ outp) {
    extern __shared__ char smem[];
    const uint32_t sb = smem_u32(smem);

    const int tid  = threadIdx.x;
    const int lane = tid & 31, wid = tid >> 5;
    const int bm = blockIdx.y * 128;
    const int bn = blockIdx.x * 128;

    const __nv_bfloat16* Ah_ = (MODE == 0) ? g_xhi   : g_vhi;
    const __nv_bfloat16* Al_ = (MODE == 0) ? g_xlo   : g_vlo;
    const __nv_bfloat16* Bh_ = (MODE == 0) ? g_wvthi : g_wohi;
    const __nv_bfloat16* Bl_ = (MODE == 0) ? g_wvtlo : g_wolo;

    // gather constants (MODE 1): m = bm + row -> b = bm>>11, h = (bm&2047)>>7, r = row
    const int boff = (bm >> 11) << 11;          // b * 2048
    const int hoff = ((bm & 2047) >> 7) * 64;   // h * 64

    // ---- global -> smem stage loader (cp.async), one commit group per stage
    const int seg  = tid & 3;        // 16B segment within 64B (BK=32 bf16) row
    const int row0 = tid >> 2;       // 0..31

    auto issue = [&](int c) {
        const uint32_t sbase = sb + (uint32_t)(c & 1) * STG_BYTES;
#pragma unroll
        for (int i = 0; i < 4; i++) {
            const int row = row0 + 32 * i;
            size_t aoff;
            if (MODE == 0) {
                aoff = (size_t)(bm + row) * DD + c * 32 + seg * 8;
            } else {
                aoff = (size_t)(boff + row * 16 + (c >> 1)) * DD
                     + hoff + (c & 1) * 32 + seg * 8;
            }
            const size_t boff2 = (size_t)(bn + row) * DD + c * 32 + seg * 8;
            const uint32_t sA = sbase + OFF_AH + row * (KS * 2) + seg * 16;
            const uint32_t sB = sbase + OFF_BH + row * (KS * 2) + seg * 16;
            CP16(sA,            Ah_ + aoff);
            CP16(sA + STG_MAT,  Al_ + aoff);
            CP16(sB,            Bh_ + boff2);
            CP16(sB + STG_MAT,  Bl_ + boff2);
        }
        CP_COMMIT();
    };

    // ---- warp tiling: 2x2 warps of 64x64
    const int warp_m = (wid >> 1) * 64;
    const int warp_n = (wid & 1) * 64;
    const int lr = lane & 15;            // ldmatrix row within 16
    const int lcb = (lane >> 4) * 16;    // ldmatrix k-half byte offset (8 bf16)

    float acc[4][8][4];
#pragma unroll
    for (int mt = 0; mt < 4; mt++)
#pragma unroll
        for (int j = 0; j < 8; j++)
#pragma unroll
            for (int q = 0; q < 4; q++) acc[mt][j][q] = 0.f;

    issue(0);

    for (int c = 0; c < NCHUNK; c++) {
        if (c + 1 < NCHUNK) { issue(c + 1); CP_WAIT1(); }
        else                { CP_WAIT0(); }
        __syncthreads();

        const uint32_t sbase = sb + (uint32_t)(c & 1) * STG_BYTES;
#pragma unroll
        for (int kk = 0; kk < 2; kk++) {
            const uint32_t kb = kk * 32 + lcb;  // k byte offset within row
            uint32_t aAddr[4], bAddr[4];
#pragma unroll
            for (int mt = 0; mt < 4; mt++)
                aAddr[mt] = sbase + (warp_m + mt * 16 + lr) * (KS * 2) + kb;
#pragma unroll
            for (int nt = 0; nt < 4; nt++)
                bAddr[nt] = sbase + OFF_BH + (warp_n + nt * 16 + lr) * (KS * 2) + kb;

            uint32_t ah[4][4], bb[4][4];
            // pass 1: Ah x Bh
#pragma unroll
            for (int mt = 0; mt < 4; mt++) LDSM4(ah[mt], aAddr[mt] + OFF_AH);
#pragma unroll
            for (int nt = 0; nt < 4; nt++) LDSM4(bb[nt], bAddr[nt]);
#pragma unroll
            for (int mt = 0; mt < 4; mt++)
#pragma unroll
                for (int nt = 0; nt < 4; nt++) {
                    MMA(acc[mt][2 * nt],     ah[mt], bb[nt][0], bb[nt][2]);
                    MMA(acc[mt][2 * nt + 1], ah[mt], bb[nt][1], bb[nt][3]);
                }
            // pass 2: Ah x Bl (reuse b regs)
#pragma unroll
            for (int nt = 0; nt < 4; nt++) LDSM4(bb[nt], bAddr[nt] + (OFF_BL - OFF_BH));
#pragma unroll
            for (int mt = 0; mt < 4; mt++)
#pragma unroll
                for (int nt = 0; nt < 4; nt++) {
                    MMA(acc[mt][2 * nt],     ah[mt], bb[nt][0], bb[nt][2]);
                    MMA(acc[mt][2 * nt + 1], ah[mt], bb[nt][1], bb[nt][3]);
                }
            // pass 3: Al x Bh (reuse a regs, reload Bh)
#pragma unroll
            for (int mt = 0; mt < 4; mt++) LDSM4(ah[mt], aAddr[mt] + OFF_AL);
#pragma unroll
            for (int nt = 0; nt < 4; nt++) LDSM4(bb[nt], bAddr[nt]);
#pragma unroll
            for (int mt = 0; mt < 4; mt++)
#pragma unroll
                for (int nt = 0; nt < 4; nt++) {
                    MMA(acc[mt][2 * nt],     ah[mt], bb[nt][0], bb[nt][2]);
                    MMA(acc[mt][2 * nt + 1], ah[mt], bb[nt][1], bb[nt][3]);
                }
        }
        __syncthreads();
    }

    // ---- epilogue
    // d0,d1 -> (m = base + lane/4,      n = n8 + 2*(lane&3) + {0,1})
    // d2,d3 -> (m = base + lane/4 + 8,  same n)
#pragma unroll
    for (int mt = 0; mt < 4; mt++) {
        const int m0 = bm + warp_m + mt * 16 + (lane >> 2);
#pragma unroll
        for (int j = 0; j < 8; j++) {
            const int n0 = bn + warp_n + j * 8 + (lane & 3) * 2;
            const float* d = acc[mt][j];
            if (MODE == 0) {
#pragma unroll
                for (int half = 0; half < 2; half++) {
                    const size_t o = (size_t)(m0 + 8 * half) * DD + n0;
                    float f0 = d[2 * half], f1 = d[2 * half + 1];
                    __nv_bfloat162 h = __float22bfloat162_rn(make_float2(f0, f1));
                    __nv_bfloat162 l = __float22bfloat162_rn(
                        make_float2(f0 - __bfloat162float(h.x),
                                    f1 - __bfloat162float(h.y)));
                    *(__nv_bfloat162*)&g_vhi[o] = h;
                    *(__nv_bfloat162*)&g_vlo[o] = l;
                }
            } else {
#pragma unroll
                for (int half = 0; half < 2; half++) {
                    const size_t o = (size_t)(m0 + 8 * half) * DD + n0;
                    *(float2*)&outp[o] = make_float2(d[2 * half], d[2 * half + 1]);
                }
            }
        }
    }
}

// ------------------------------------------------------------------ prep
static __device__ __forceinline__ void split1(float f, ushort& h, ushort& l) {
    __nv_bfloat16 hb = __float2bfloat16(f);
    __nv_bfloat16 lb = __float2bfloat16(f - __bfloat162float(hb));
    h = __bfloat16_as_ushort(hb);
    l = __bfloat16_as_ushort(lb);
}

__global__ void k_split_x(const float* __restrict__ in) {
    const int i = blockIdx.x * 256 + threadIdx.x;
    float4 v = ((const float4*)in)[i];
    ushort h0, h1, h2, h3, l0, l1, l2, l3;
    split1(v.x, h0, l0); split1(v.y, h1, l1); split1(v.z, h2, l2); split1(v.w, h3, l3);
    ((uint2*)g_xhi)[i] = make_uint2((uint32_t)h0 | ((uint32_t)h1 << 16),
                                    (uint32_t)h2 | ((uint32_t)h3 << 16));
    ((uint2*)g_xlo)[i] = make_uint2((uint32_t)l0 | ((uint32_t)l1 << 16),
                                    (uint32_t)l2 | ((uint32_t)l3 << 16));
}

__global__ void k_split_wo(const float* __restrict__ in) {
    const int i = blockIdx.x * 256 + threadIdx.x;
    float4 v = ((const float4*)in)[i];
    ushort h0, h1, h2, h3, l0, l1, l2, l3;
    split1(v.x, h0, l0); split1(v.y, h1, l1); split1(v.z, h2, l2); split1(v.w, h3, l3);
    ((uint2*)g_wohi)[i] = make_uint2((uint32_t)h0 | ((uint32_t)h1 << 16),
                                     (uint32_t)h2 | ((uint32_t)h3 << 16));
    ((uint2*)g_wolo)[i] = make_uint2((uint32_t)l0 | ((uint32_t)l1 << 16),
                                     (uint32_t)l2 | ((uint32_t)l3 << 16));
}

// WvT[n][k] = Wv[k][n], split hi/lo
__global__ void k_trans_wv(const float* __restrict__ W) {
    __shared__ float t[32][33];
    const int bx = blockIdx.x * 32, by = blockIdx.y * 32;
    const int tx = threadIdx.x, ty = threadIdx.y;   // (32, 8)
#pragma unroll
    for (int j = 0; j < 32; j += 8)
        t[ty + j][tx] = W[(size_t)(by + ty + j) * DD + bx + tx];
    __syncthreads();
#pragma unroll
    for (int j = 0; j < 32; j += 8) {
        ushort h, l;
        split1(t[tx][ty + j], h, l);
        const size_t o = (size_t)(bx + ty + j) * DD + by + tx;
        g_wvthi[o] = __ushort_as_bfloat16(h);
        g_wvtlo[o] = __ushort_as_bfloat16(l);
    }
}

// ------------------------------------------------------------------ launch
// inputs: x, mask, Wq, Wk, Wv, Wo -> fp32 out [B,T,D]
extern "C" void kernel_launch(void* const* d_in, const int* in_sizes, int n_in,
                              void* d_out, int out_size) {
    const float* x  = (const float*)d_in[0];
    const float* Wv = (const float*)d_in[4];
    const float* Wo = (const float*)d_in[5];
    float* out = (float*)d_out;

    cudaFuncSetAttribute(gemm_hmma<0>, cudaFuncAttributeMaxDynamicSharedMemorySize, SMEM_SZ);
    cudaFuncSetAttribute(gemm_hmma<1>, cudaFuncAttributeMaxDynamicSharedMemorySize, SMEM_SZ);

    k_split_x<<<(MTOT * DD / 4) / 256, 256>>>(x);
    k_trans_wv<<<dim3(32, 32), dim3(32, 8)>>>(Wv);
    k_split_wo<<<(DD * DD / 4) / 256, 256>>>(Wo);

    dim3 grid(DD / 128, MTOT / 128);   // (8, 32) = 256 CTAs
    gemm_hmma<0><<<grid, 128, SMEM_SZ>>>(nullptr);
    gemm_hmma<1><<<grid, 128, SMEM_SZ>>>(out);
}

// round 4
// speedup vs baseline: 2.2748x; 1.0114x over previous
#include <cuda_runtime.h>
#include <cuda_bf16.h>
#include <cstdint>

// y = gather_perm(x @ Wv) @ Wo^T   (softmax rowsum == 1 collapse, validated R1)
// tcgen05 unavailable (harness targets sm_103 without 'a') => mma.sync bf16 path.
// Precision: bf16 hi/lo split, C = Ah*Bh + Ah*Bl + Al*Bh  (rel_err ~9e-6, R3)
// R4 change: 256 threads / 8 warps per CTA (warp tile 64x32), 2 CTAs/SM
//            to fix the latency-bound profile (occ 10.4%, issue 23.6%).

#define MTOT 4096
#define DD   1024
#define KS   40                  // padded smem row stride (bf16): 80B, conflict-free
#define STG_MAT  (128 * KS * 2)  // 10240 B per matrix tile
#define OFF_AH   0
#define OFF_AL   (1 * STG_MAT)
#define OFF_BH   (2 * STG_MAT)
#define OFF_BL   (3 * STG_MAT)
#define STG_BYTES (4 * STG_MAT)  // 40960 B / stage
#define SMEM_SZ   (2 * STG_BYTES)
#define NCHUNK   (DD / 32)       // 32 k-chunks of BK=32

__device__ __nv_bfloat16 g_xhi[MTOT * DD], g_xlo[MTOT * DD];
__device__ __nv_bfloat16 g_wvthi[DD * DD], g_wvtlo[DD * DD];
__device__ __nv_bfloat16 g_wohi[DD * DD],  g_wolo[DD * DD];
__device__ __nv_bfloat16 g_vhi[MTOT * DD], g_vlo[MTOT * DD];

// ------------------------------------------------------------------ asm utils
static __device__ __forceinline__ uint32_t smem_u32(const void* p) {
    uint32_t a;
    asm("{ .reg .u64 t; cvta.to.shared.u64 t, %1; cvt.u32.u64 %0, t; }" : "=r"(a) : "l"(p));
    return a;
}
#define CP16(s, g) \
    asm volatile("cp.async.cg.shared.global [%0], [%1], 16;" :: "r"(s), "l"(g))
#define CP_COMMIT() asm volatile("cp.async.commit_group;")
#define CP_WAIT1()  asm volatile("cp.async.wait_group 1;")
#define CP_WAIT0()  asm volatile("cp.async.wait_group 0;")

#define LDSM4(r, addr) \
    asm volatile("ldmatrix.sync.aligned.m8n8.x4.shared.b16 {%0,%1,%2,%3}, [%4];" \
                 : "=r"((r)[0]), "=r"((r)[1]), "=r"((r)[2]), "=r"((r)[3]) : "r"(addr))

#define MMA(d, a, b0, b1) \
    asm volatile("mma.sync.aligned.m16n8k16.row.col.f32.bf16.bf16.f32 " \
                 "{%0,%1,%2,%3}, {%4,%5,%6,%7}, {%8,%9}, {%0,%1,%2,%3};" \
                 : "+f"((d)[0]), "+f"((d)[1]), "+f"((d)[2]), "+f"((d)[3]) \
                 : "r"((a)[0]), "r"((a)[1]), "r"((a)[2]), "r"((a)[3]), "r"(b0), "r"(b1))

// ------------------------------------------------------------------ GEMM
// MODE 0: V = x @ WvT^T  (A = g_xhi/lo [m][k], B = g_wvthi/lo [n][k]) -> g_vhi/lo
// MODE 1: out = gather(V) @ Wo^T (A gathered from g_vhi/lo, B = g_wohi/lo) -> fp32
template<int MODE>
__global__ void __launch_bounds__(256, 2)
gemm_hmma(float* __restrict__ outp) {
    extern __shared__ char smem[];
    const uint32_t sb = smem_u32(smem);

    const int tid  = threadIdx.x;
    const int lane = tid & 31, wid = tid >> 5;
    const int bm = blockIdx.y * 128;
    const int bn = blockIdx.x * 128;

    const __nv_bfloat16* Ah_ = (MODE == 0) ? g_xhi   : g_vhi;
    const __nv_bfloat16* Al_ = (MODE == 0) ? g_xlo   : g_vlo;
    const __nv_bfloat16* Bh_ = (MODE == 0) ? g_wvthi : g_wohi;
    const __nv_bfloat16* Bl_ = (MODE == 0) ? g_wvtlo : g_wolo;

    // gather constants (MODE 1): m = bm + row -> b = bm>>11, h = (bm&2047)>>7
    const int boff = (bm >> 11) << 11;          // b * 2048
    const int hoff = ((bm & 2047) >> 7) * 64;   // h * 64

    // ---- global -> smem stage loader: 256 threads, 8 CP16 per thread
    const int seg  = tid & 3;        // 16B segment within 64B (BK=32 bf16) row
    const int row0 = tid >> 2;       // 0..63

    auto issue = [&](int c) {
        const uint32_t sbase = sb + (uint32_t)(c & 1) * STG_BYTES;
#pragma unroll
        for (int i = 0; i < 2; i++) {
            const int row = row0 + 64 * i;
            size_t aoff;
            if (MODE == 0) {
                aoff = (size_t)(bm + row) * DD + c * 32 + seg * 8;
            } else {
                aoff = (size_t)(boff + row * 16 + (c >> 1)) * DD
                     + hoff + (c & 1) * 32 + seg * 8;
            }
            const size_t boff2 = (size_t)(bn + row) * DD + c * 32 + seg * 8;
            const uint32_t sA = sbase + OFF_AH + row * (KS * 2) + seg * 16;
            const uint32_t sB = sbase + OFF_BH + row * (KS * 2) + seg * 16;
            CP16(sA,            Ah_ + aoff);
            CP16(sA + STG_MAT,  Al_ + aoff);
            CP16(sB,            Bh_ + boff2);
            CP16(sB + STG_MAT,  Bl_ + boff2);
        }
        CP_COMMIT();
    };

    // ---- warp tiling: 2(m) x 4(n) warps of 64x32
    const int warp_m = (wid >> 2) * 64;
    const int warp_n = (wid & 3) * 32;
    const int lr = lane & 15;            // ldmatrix row within 16
    const int lcb = (lane >> 4) * 16;    // ldmatrix k-half byte offset

    float acc[4][4][4];
#pragma unroll
    for (int mt = 0; mt < 4; mt++)
#pragma unroll
        for (int j = 0; j < 4; j++)
#pragma unroll
            for (int q = 0; q < 4; q++) acc[mt][j][q] = 0.f;

    issue(0);

    for (int c = 0; c < NCHUNK; c++) {
        if (c + 1 < NCHUNK) { issue(c + 1); CP_WAIT1(); }
        else                { CP_WAIT0(); }
        __syncthreads();

        const uint32_t sbase = sb + (uint32_t)(c & 1) * STG_BYTES;
#pragma unroll
        for (int kk = 0; kk < 2; kk++) {
            const uint32_t kb = kk * 32 + lcb;  // k byte offset within row
            uint32_t aAddr[4], bAddr[2];
#pragma unroll
            for (int mt = 0; mt < 4; mt++)
                aAddr[mt] = sbase + (warp_m + mt * 16 + lr) * (KS * 2) + kb;
#pragma unroll
            for (int nt = 0; nt < 2; nt++)
                bAddr[nt] = sbase + OFF_BH + (warp_n + nt * 16 + lr) * (KS * 2) + kb;

            uint32_t ah[4][4], bb[2][4];
            // pass 1: Ah x Bh
#pragma unroll
            for (int mt = 0; mt < 4; mt++) LDSM4(ah[mt], aAddr[mt] + OFF_AH);
#pragma unroll
            for (int nt = 0; nt < 2; nt++) LDSM4(bb[nt], bAddr[nt]);
#pragma unroll
            for (int mt = 0; mt < 4; mt++)
#pragma unroll
                for (int nt = 0; nt < 2; nt++) {
                    MMA(acc[mt][2 * nt],     ah[mt], bb[nt][0], bb[nt][2]);
                    MMA(acc[mt][2 * nt + 1], ah[mt], bb[nt][1], bb[nt][3]);
                }
            // pass 2: Ah x Bl (reuse a regs)
#pragma unroll
            for (int nt = 0; nt < 2; nt++) LDSM4(bb[nt], bAddr[nt] + (OFF_BL - OFF_BH));
#pragma unroll
            for (int mt = 0; mt < 4; mt++)
#pragma unroll
                for (int nt = 0; nt < 2; nt++) {
                    MMA(acc[mt][2 * nt],     ah[mt], bb[nt][0], bb[nt][2]);
                    MMA(acc[mt][2 * nt + 1], ah[mt], bb[nt][1], bb[nt][3]);
                }
            // pass 3: Al x Bh (reload a, reload bh)
#pragma unroll
            for (int mt = 0; mt < 4; mt++) LDSM4(ah[mt], aAddr[mt] + OFF_AL);
#pragma unroll
            for (int nt = 0; nt < 2; nt++) LDSM4(bb[nt], bAddr[nt]);
#pragma unroll
            for (int mt = 0; mt < 4; mt++)
#pragma unroll
                for (int nt = 0; nt < 2; nt++) {
                    MMA(acc[mt][2 * nt],     ah[mt], bb[nt][0], bb[nt][2]);
                    MMA(acc[mt][2 * nt + 1], ah[mt], bb[nt][1], bb[nt][3]);
                }
        }
        __syncthreads();
    }

    // ---- epilogue (fragment layout: d0,d1 -> row lane>>2, d2,d3 -> +8)
#pragma unroll
    for (int mt = 0; mt < 4; mt++) {
        const int m0 = bm + warp_m + mt * 16 + (lane >> 2);
#pragma unroll
        for (int j = 0; j < 4; j++) {
            const int n0 = bn + warp_n + j * 8 + (lane & 3) * 2;
            const float* d = acc[mt][j];
            if (MODE == 0) {
#pragma unroll
                for (int half = 0; half < 2; half++) {
                    const size_t o = (size_t)(m0 + 8 * half) * DD + n0;
                    float f0 = d[2 * half], f1 = d[2 * half + 1];
                    __nv_bfloat162 h = __float22bfloat162_rn(make_float2(f0, f1));
                    __nv_bfloat162 l = __float22bfloat162_rn(
                        make_float2(f0 - __bfloat162float(h.x),
                                    f1 - __bfloat162float(h.y)));
                    *(__nv_bfloat162*)&g_vhi[o] = h;
                    *(__nv_bfloat162*)&g_vlo[o] = l;
                }
            } else {
#pragma unroll
                for (int half = 0; half < 2; half++) {
                    const size_t o = (size_t)(m0 + 8 * half) * DD + n0;
                    *(float2*)&outp[o] = make_float2(d[2 * half], d[2 * half + 1]);
                }
            }
        }
    }
}

// ------------------------------------------------------------------ prep
static __device__ __forceinline__ void split1(float f, ushort& h, ushort& l) {
    __nv_bfloat16 hb = __float2bfloat16(f);
    __nv_bfloat16 lb = __float2bfloat16(f - __bfloat162float(hb));
    h = __bfloat16_as_ushort(hb);
    l = __bfloat16_as_ushort(lb);
}

__global__ void k_split_x(const float* __restrict__ in) {
    const int i = blockIdx.x * 256 + threadIdx.x;
    float4 v = ((const float4*)in)[i];
    ushort h0, h1, h2, h3, l0, l1, l2, l3;
    split1(v.x, h0, l0); split1(v.y, h1, l1); split1(v.z, h2, l2); split1(v.w, h3, l3);
    ((uint2*)g_xhi)[i] = make_uint2((uint32_t)h0 | ((uint32_t)h1 << 16),
                                    (uint32_t)h2 | ((uint32_t)h3 << 16));
    ((uint2*)g_xlo)[i] = make_uint2((uint32_t)l0 | ((uint32_t)l1 << 16),
                                    (uint32_t)l2 | ((uint32_t)l3 << 16));
}

__global__ void k_split_wo(const float* __restrict__ in) {
    const int i = blockIdx.x * 256 + threadIdx.x;
    float4 v = ((const float4*)in)[i];
    ushort h0, h1, h2, h3, l0, l1, l2, l3;
    split1(v.x, h0, l0); split1(v.y, h1, l1); split1(v.z, h2, l2); split1(v.w, h3, l3);
    ((uint2*)g_wohi)[i] = make_uint2((uint32_t)h0 | ((uint32_t)h1 << 16),
                                     (uint32_t)h2 | ((uint32_t)h3 << 16));
    ((uint2*)g_wolo)[i] = make_uint2((uint32_t)l0 | ((uint32_t)l1 << 16),
                                     (uint32_t)l2 | ((uint32_t)l3 << 16));
}

// WvT[n][k] = Wv[k][n], split hi/lo
__global__ void k_trans_wv(const float* __restrict__ W) {
    __shared__ float t[32][33];
    const int bx = blockIdx.x * 32, by = blockIdx.y * 32;
    const int tx = threadIdx.x, ty = threadIdx.y;   // (32, 8)
#pragma unroll
    for (int j = 0; j < 32; j += 8)
        t[ty + j][tx] = W[(size_t)(by + ty + j) * DD + bx + tx];
    __syncthreads();
#pragma unroll
    for (int j = 0; j < 32; j += 8) {
        ushort h, l;
        split1(t[tx][ty + j], h, l);
        const size_t o = (size_t)(bx + ty + j) * DD + by + tx;
        g_wvthi[o] = __ushort_as_bfloat16(h);
        g_wvtlo[o] = __ushort_as_bfloat16(l);
    }
}

// ------------------------------------------------------------------ launch
// inputs: x, mask, Wq, Wk, Wv, Wo -> fp32 out [B,T,D]
extern "C" void kernel_launch(void* const* d_in, const int* in_sizes, int n_in,
                              void* d_out, int out_size) {
    const float* x  = (const float*)d_in[0];
    const float* Wv = (const float*)d_in[4];
    const float* Wo = (const float*)d_in[5];
    float* out = (float*)d_out;

    cudaFuncSetAttribute(gemm_hmma<0>, cudaFuncAttributeMaxDynamicSharedMemorySize, SMEM_SZ);
    cudaFuncSetAttribute(gemm_hmma<1>, cudaFuncAttributeMaxDynamicSharedMemorySize, SMEM_SZ);

    k_split_x<<<(MTOT * DD / 4) / 256, 256>>>(x);
    k_trans_wv<<<dim3(32, 32), dim3(32, 8)>>>(Wv);
    k_split_wo<<<(DD * DD / 4) / 256, 256>>>(Wo);

    dim3 grid(DD / 128, MTOT / 128);   // (8, 32) = 256 CTAs
    gemm_hmma<0><<<grid, 256, SMEM_SZ>>>(nullptr);
    gemm_hmma<1><<<grid, 256, SMEM_SZ>>>(out);
}

// round 5
// speedup vs baseline: 3.0576x; 1.3441x over previous
#include <cuda_runtime.h>
#include <cuda_fp16.h>
#include <cstdint>

// y = gather_perm(x @ Wv) @ Wo^T   (softmax rowsum == 1 collapse, validated R1)
// tcgen05 unavailable (harness targets sm_103, no 'a') => mma.sync path.
// R5: fp16 2-pass asymmetric split  C = Ah*B + Al*B  (u_fp16=2^-11; B unsplit
//     error ~u/sqrt(3)=2.8e-4/GEMM, ~4e-4 total vs 1e-3 gate; rms model
//     validated on R3/R4: predicted 8.8e-6, measured 8.966e-6).
//     -33% HMMA, -29% smem reads, full fragment retention + front-loaded LDSM.

#define MTOT 4096
#define DD   1024
#define KS   40                  // padded smem row stride (fp16): 80B, conflict-free
#define STG_MAT  (128 * KS * 2)  // 10240 B per matrix tile
#define OFF_AH   0
#define OFF_AL   (1 * STG_MAT)
#define OFF_B    (2 * STG_MAT)
#define STG_BYTES (3 * STG_MAT)  // 30720 B / stage
#define SMEM_SZ   (2 * STG_BYTES)
#define NCHUNK   (DD / 32)       // 32 k-chunks of BK=32

__device__ __half g_xh[MTOT * DD], g_xl[MTOT * DD];
__device__ __half g_wvt[DD * DD];          // WvT, single fp16
__device__ __half g_wo[DD * DD];           // Wo,  single fp16
__device__ __half g_vh[MTOT * DD], g_vl[MTOT * DD];

// ------------------------------------------------------------------ asm utils
static __device__ __forceinline__ uint32_t smem_u32(const void* p) {
    uint32_t a;
    asm("{ .reg .u64 t; cvta.to.shared.u64 t, %1; cvt.u32.u64 %0, t; }" : "=r"(a) : "l"(p));
    return a;
}
#define CP16(s, g) \
    asm volatile("cp.async.cg.shared.global [%0], [%1], 16;" :: "r"(s), "l"(g))
#define CP_COMMIT() asm volatile("cp.async.commit_group;")
#define CP_WAIT1()  asm volatile("cp.async.wait_group 1;")
#define CP_WAIT0()  asm volatile("cp.async.wait_group 0;")

#define LDSM4(r, addr) \
    asm volatile("ldmatrix.sync.aligned.m8n8.x4.shared.b16 {%0,%1,%2,%3}, [%4];" \
                 : "=r"((r)[0]), "=r"((r)[1]), "=r"((r)[2]), "=r"((r)[3]) : "r"(addr))

#define MMA(d, a, b0, b1) \
    asm volatile("mma.sync.aligned.m16n8k16.row.col.f32.f16.f16.f32 " \
                 "{%0,%1,%2,%3}, {%4,%5,%6,%7}, {%8,%9}, {%0,%1,%2,%3};" \
                 : "+f"((d)[0]), "+f"((d)[1]), "+f"((d)[2]), "+f"((d)[3]) \
                 : "r"((a)[0]), "r"((a)[1]), "r"((a)[2]), "r"((a)[3]), "r"(b0), "r"(b1))

// ------------------------------------------------------------------ GEMM
// MODE 0: V = x @ WvT^T  (A = g_xh/g_xl [m][k], B = g_wvt [n][k]) -> g_vh/g_vl
// MODE 1: out = gather(V) @ Wo^T (A gathered from g_vh/g_vl, B = g_wo) -> fp32
template<int MODE>
__global__ void __launch_bounds__(256, 2)
gemm_hmma(float* __restrict__ outp) {
    extern __shared__ char smem[];
    const uint32_t sb = smem_u32(smem);

    const int tid  = threadIdx.x;
    const int lane = tid & 31, wid = tid >> 5;
    const int bm = blockIdx.y * 128;
    const int bn = blockIdx.x * 128;

    const __half* Ah_ = (MODE == 0) ? g_xh  : g_vh;
    const __half* Al_ = (MODE == 0) ? g_xl  : g_vl;
    const __half* B_  = (MODE == 0) ? g_wvt : g_wo;

    // gather constants (MODE 1): m = bm + row -> b = bm>>11, h = (bm&2047)>>7
    const int boff = (bm >> 11) << 11;          // b * 2048
    const int hoff = ((bm & 2047) >> 7) * 64;   // h * 64

    // ---- global -> smem stage loader: 256 threads, 6 CP16 per thread
    const int seg  = tid & 3;        // 16B segment within 64B (BK=32 fp16) row
    const int row0 = tid >> 2;       // 0..63

    auto issue = [&](int c) {
        const uint32_t sbase = sb + (uint32_t)(c & 1) * STG_BYTES;
#pragma unroll
        for (int i = 0; i < 2; i++) {
            const int row = row0 + 64 * i;
            size_t aoff;
            if (MODE == 0) {
                aoff = (size_t)(bm + row) * DD + c * 32 + seg * 8;
            } else {
                aoff = (size_t)(boff + row * 16 + (c >> 1)) * DD
                     + hoff + (c & 1) * 32 + seg * 8;
            }
            const size_t boff2 = (size_t)(bn + row) * DD + c * 32 + seg * 8;
            const uint32_t sA = sbase + OFF_AH + row * (KS * 2) + seg * 16;
            CP16(sA,           Ah_ + aoff);
            CP16(sA + STG_MAT, Al_ + aoff);
            CP16(sbase + OFF_B + row * (KS * 2) + seg * 16, B_ + boff2);
        }
        CP_COMMIT();
    };

    // ---- warp tiling: 2(m) x 4(n) warps of 64x32
    const int warp_m = (wid >> 2) * 64;
    const int warp_n = (wid & 3) * 32;
    const int lr = lane & 15;            // ldmatrix row within 16
    const int lcb = (lane >> 4) * 16;    // ldmatrix k-half byte offset

    float acc[4][4][4];
#pragma unroll
    for (int mt = 0; mt < 4; mt++)
#pragma unroll
        for (int j = 0; j < 4; j++)
#pragma unroll
            for (int q = 0; q < 4; q++) acc[mt][j][q] = 0.f;

    issue(0);

    for (int c = 0; c < NCHUNK; c++) {
        if (c + 1 < NCHUNK) { issue(c + 1); CP_WAIT1(); }
        else                { CP_WAIT0(); }
        __syncthreads();

        const uint32_t sbase = sb + (uint32_t)(c & 1) * STG_BYTES;
#pragma unroll
        for (int kk = 0; kk < 2; kk++) {
            const uint32_t kb = kk * 32 + lcb;  // k byte offset within row

            // ---- front-load ALL fragments for this kk (10 independent LDSM)
            uint32_t ah[4][4], al[4][4], bb[2][4];
#pragma unroll
            for (int mt = 0; mt < 4; mt++) {
                const uint32_t aAddr = sbase + (warp_m + mt * 16 + lr) * (KS * 2) + kb;
                LDSM4(ah[mt], aAddr + OFF_AH);
                LDSM4(al[mt], aAddr + OFF_AL);
            }
#pragma unroll
            for (int nt = 0; nt < 2; nt++) {
                const uint32_t bAddr = sbase + OFF_B +
                                       (warp_n + nt * 16 + lr) * (KS * 2) + kb;
                LDSM4(bb[nt], bAddr);
            }

            // pass 1: Ah x B
#pragma unroll
            for (int mt = 0; mt < 4; mt++)
#pragma unroll
                for (int nt = 0; nt < 2; nt++) {
                    MMA(acc[mt][2 * nt],     ah[mt], bb[nt][0], bb[nt][2]);
                    MMA(acc[mt][2 * nt + 1], ah[mt], bb[nt][1], bb[nt][3]);
                }
            // pass 2: Al x B (all regs retained)
#pragma unroll
            for (int mt = 0; mt < 4; mt++)
#pragma unroll
                for (int nt = 0; nt < 2; nt++) {
                    MMA(acc[mt][2 * nt],     al[mt], bb[nt][0], bb[nt][2]);
                    MMA(acc[mt][2 * nt + 1], al[mt], bb[nt][1], bb[nt][3]);
                }
        }
        __syncthreads();
    }

    // ---- epilogue (fragment layout: d0,d1 -> row lane>>2, d2,d3 -> +8)
#pragma unroll
    for (int mt = 0; mt < 4; mt++) {
        const int m0 = bm + warp_m + mt * 16 + (lane >> 2);
#pragma unroll
        for (int j = 0; j < 4; j++) {
            const int n0 = bn + warp_n + j * 8 + (lane & 3) * 2;
            const float* d = acc[mt][j];
            if (MODE == 0) {
#pragma unroll
                for (int half_ = 0; half_ < 2; half_++) {
                    const size_t o = (size_t)(m0 + 8 * half_) * DD + n0;
                    float f0 = d[2 * half_], f1 = d[2 * half_ + 1];
                    __half h0 = __float2half_rn(f0);
                    __half h1 = __float2half_rn(f1);
                    __half l0 = __float2half_rn(f0 - __half2float(h0));
                    __half l1 = __float2half_rn(f1 - __half2float(h1));
                    *(__half2*)&g_vh[o] = __halves2half2(h0, h1);
                    *(__half2*)&g_vl[o] = __halves2half2(l0, l1);
                }
            } else {
#pragma unroll
                for (int half_ = 0; half_ < 2; half_++) {
                    const size_t o = (size_t)(m0 + 8 * half_) * DD + n0;
                    *(float2*)&outp[o] = make_float2(d[2 * half_], d[2 * half_ + 1]);
                }
            }
        }
    }
}

// ------------------------------------------------------------------ prep
__global__ void k_split_x(const float* __restrict__ in) {
    const int i = blockIdx.x * 256 + threadIdx.x;   // over float4s
    float4 v = ((const float4*)in)[i];
    __half h0 = __float2half_rn(v.x), h1 = __float2half_rn(v.y);
    __half h2 = __float2half_rn(v.z), h3 = __float2half_rn(v.w);
    __half l0 = __float2half_rn(v.x - __half2float(h0));
    __half l1 = __float2half_rn(v.y - __half2float(h1));
    __half l2 = __float2half_rn(v.z - __half2float(h2));
    __half l3 = __float2half_rn(v.w - __half2float(h3));
    ((__half2*)g_xh)[2 * i]     = __halves2half2(h0, h1);
    ((__half2*)g_xh)[2 * i + 1] = __halves2half2(h2, h3);
    ((__half2*)g_xl)[2 * i]     = __halves2half2(l0, l1);
    ((__half2*)g_xl)[2 * i + 1] = __halves2half2(l2, l3);
}

__global__ void k_conv_wo(const float* __restrict__ in) {
    const int i = blockIdx.x * 256 + threadIdx.x;
    float4 v = ((const float4*)in)[i];
    ((__half2*)g_wo)[2 * i]     = __floats2half2_rn(v.x, v.y);
    ((__half2*)g_wo)[2 * i + 1] = __floats2half2_rn(v.z, v.w);
}

// WvT[n][k] = Wv[k][n], single fp16
__global__ void k_trans_wv(const float* __restrict__ W) {
    __shared__ float t[32][33];
    const int bx = blockIdx.x * 32, by = blockIdx.y * 32;
    const int tx = threadIdx.x, ty = threadIdx.y;   // (32, 8)
#pragma unroll
    for (int j = 0; j < 32; j += 8)
        t[ty + j][tx] = W[(size_t)(by + ty + j) * DD + bx + tx];
    __syncthreads();
#pragma unroll
    for (int j = 0; j < 32; j += 8) {
        const size_t o = (size_t)(bx + ty + j) * DD + by + tx;
        g_wvt[o] = __float2half_rn(t[tx][ty + j]);
    }
}

// ------------------------------------------------------------------ launch
// inputs: x, mask, Wq, Wk, Wv, Wo -> fp32 out [B,T,D]
extern "C" void kernel_launch(void* const* d_in, const int* in_sizes, int n_in,
                              void* d_out, int out_size) {
    const float* x  = (const float*)d_in[0];
    const float* Wv = (const float*)d_in[4];
    const float* Wo = (const float*)d_in[5];
    float* out = (float*)d_out;

    cudaFuncSetAttribute(gemm_hmma<0>, cudaFuncAttributeMaxDynamicSharedMemorySize, SMEM_SZ);
    cudaFuncSetAttribute(gemm_hmma<1>, cudaFuncAttributeMaxDynamicSharedMemorySize, SMEM_SZ);

    k_split_x<<<(MTOT * DD / 4) / 256, 256>>>(x);
    k_trans_wv<<<dim3(32, 32), dim3(32, 8)>>>(Wv);
    k_conv_wo<<<(DD * DD / 4) / 256, 256>>>(Wo);

    dim3 grid(DD / 128, MTOT / 128);   // (8, 32) = 256 CTAs
    gemm_hmma<0><<<grid, 256, SMEM_SZ>>>(nullptr);
    gemm_hmma<1><<<grid, 256, SMEM_SZ>>>(out);
}